// round 10
// baseline (speedup 1.0000x reference)
#include <cuda_runtime.h>
#include <cuda_bf16.h>
#include <math.h>

// Problem constants
#define D_    64
#define L_    64
#define M_    192          // 3*L nodes per dialogue
#define DIM_  512
#define G_    256
#define N_    4096         // D*L
#define KTOP  12           // int(64*0.2)
#define INV_TAU (1.0f/0.07f)

// ---------------- scratch (static __device__ arrays: allocation-free) ------
__device__ float g_gram[D_*M_*M_];     // per-dialogue gram
__device__ float g_sq[D_*M_];          // gram diagonal (squared norms)
__device__ float g_H[D_*M_*M_];        // incidence (0/1), [d][e][n]
__device__ float g_Ht[D_*M_*M_];       // transpose [d][n][e]
__device__ float g_dege[D_*M_];
__device__ float g_degv[D_*M_];
__device__ float g_X[D_*M_*G_];
__device__ float g_E[D_*M_*G_];
__device__ float g_Y[D_*M_*G_];
__device__ float g_xn[3*N_*G_];        // normalized tn/an/vn (fp32, for loss diag)
__device__ __nv_bfloat16 g_xnh[3*N_*G_];  // bf16 copy for tensor-core sims
__device__ float g_rowsum[3*N_];
__device__ float g_colsum[3*N_];
__device__ float g_lossacc;
__device__ int   g_loss_ct;

// ---------------- helpers ---------------------------------------------------
__device__ __forceinline__ unsigned f2tf(float x) {
    unsigned u;
    asm("cvt.rna.tf32.f32 %0, %1;" : "=r"(u) : "f"(x));
    return u;
}

__device__ __forceinline__ void mma_tf32(float* c, const unsigned* a,
                                         unsigned b0, unsigned b1) {
    asm volatile(
        "mma.sync.aligned.m16n8k8.row.col.f32.tf32.tf32.f32 "
        "{%0,%1,%2,%3},{%4,%5,%6,%7},{%8,%9},{%0,%1,%2,%3};"
        : "+f"(c[0]), "+f"(c[1]), "+f"(c[2]), "+f"(c[3])
        : "r"(a[0]), "r"(a[1]), "r"(a[2]), "r"(a[3]), "r"(b0), "r"(b1));
}

__device__ __forceinline__ void mma16816(float* c, const unsigned* a,
                                         unsigned b0, unsigned b1) {
    asm volatile(
        "mma.sync.aligned.m16n8k16.row.col.f32.bf16.bf16.f32 "
        "{%0,%1,%2,%3},{%4,%5,%6,%7},{%8,%9},{%0,%1,%2,%3};"
        : "+f"(c[0]), "+f"(c[1]), "+f"(c[2]), "+f"(c[3])
        : "r"(a[0]), "r"(a[1]), "r"(a[2]), "r"(a[3]), "r"(b0), "r"(b1));
}

__device__ __forceinline__ void ldsm4(unsigned* r, unsigned addr) {
    asm volatile("ldmatrix.sync.aligned.m8n8.x4.shared.b16 {%0,%1,%2,%3},[%4];"
                 : "=r"(r[0]), "=r"(r[1]), "=r"(r[2]), "=r"(r[3]) : "r"(addr));
}
__device__ __forceinline__ void ldsm4t(unsigned* r, unsigned addr) {
    asm volatile("ldmatrix.sync.aligned.m8n8.x4.trans.shared.b16 {%0,%1,%2,%3},[%4];"
                 : "=r"(r[0]), "=r"(r[1]), "=r"(r[2]), "=r"(r[3]) : "r"(addr));
}

__device__ __forceinline__ unsigned b2u(__nv_bfloat162 h) {
    return *reinterpret_cast<unsigned*>(&h);
}

// ---------------- 3x-tf32 batched gram: gram[d] = feat_d @ feat_d^T ---------
// feat rows gathered directly from t/a/v (tile is 64-aligned => one modality).
__global__ __launch_bounds__(128)
void gram_tc(const float* __restrict__ t, const float* __restrict__ a,
             const float* __restrict__ v) {
    __shared__ unsigned Ah[64*36], Al[64*36], Bh[64*36], Bl[64*36];
    const int d = blockIdx.z;
    const int m0 = blockIdx.y * 64, n0 = blockIdx.x * 64;
    const float* srcs[3] = {t, a, v};
    const float* FA = srcs[m0 >> 6] + (long)d * L_ * DIM_;
    const float* FB = srcs[n0 >> 6] + (long)d * L_ * DIM_;
    const int tid = threadIdx.x, lane = tid & 31, wid = tid >> 5;
    const int wm = (wid >> 1) * 32, wn = (wid & 1) * 32;
    const int g = lane >> 2, c = lane & 3;
    float acc[2][4][4];
    #pragma unroll
    for (int mi = 0; mi < 2; mi++)
        #pragma unroll
        for (int ni = 0; ni < 4; ni++)
            #pragma unroll
            for (int r = 0; r < 4; r++) acc[mi][ni][r] = 0.f;

    for (int k0 = 0; k0 < DIM_; k0 += 32) {
        #pragma unroll
        for (int it = 0; it < 4; it++) {
            int idx = it * 128 + tid;
            int m = idx >> 3, kc = (idx & 7) << 2;
            float4 t4 = *(const float4*)(FA + (long)m * DIM_ + k0 + kc);
            float xs[4] = {t4.x, t4.y, t4.z, t4.w};
            #pragma unroll
            for (int j = 0; j < 4; j++) {
                unsigned h = f2tf(xs[j]);
                Ah[m*36 + kc + j] = h;
                Al[m*36 + kc + j] = f2tf(xs[j] - __uint_as_float(h));
            }
            float4 u4 = *(const float4*)(FB + (long)m * DIM_ + k0 + kc);
            float ys[4] = {u4.x, u4.y, u4.z, u4.w};
            #pragma unroll
            for (int j = 0; j < 4; j++) {
                unsigned h = f2tf(ys[j]);
                Bh[m*36 + kc + j] = h;
                Bl[m*36 + kc + j] = f2tf(ys[j] - __uint_as_float(h));
            }
        }
        __syncthreads();
        #pragma unroll
        for (int kk = 0; kk < 32; kk += 8) {
            unsigned ah[2][4], al[2][4];
            #pragma unroll
            for (int mi = 0; mi < 2; mi++) {
                int rb = wm + mi * 16;
                ah[mi][0] = Ah[(rb+g)*36 + kk+c];   al[mi][0] = Al[(rb+g)*36 + kk+c];
                ah[mi][1] = Ah[(rb+8+g)*36 + kk+c]; al[mi][1] = Al[(rb+8+g)*36 + kk+c];
                ah[mi][2] = Ah[(rb+g)*36 + kk+c+4]; al[mi][2] = Al[(rb+g)*36 + kk+c+4];
                ah[mi][3] = Ah[(rb+8+g)*36 + kk+c+4]; al[mi][3] = Al[(rb+8+g)*36 + kk+c+4];
            }
            #pragma unroll
            for (int ni = 0; ni < 4; ni++) {
                int cb = wn + ni * 8 + g;
                unsigned bh0 = Bh[cb*36 + kk+c], bh1 = Bh[cb*36 + kk+c+4];
                unsigned bl0 = Bl[cb*36 + kk+c], bl1 = Bl[cb*36 + kk+c+4];
                #pragma unroll
                for (int mi = 0; mi < 2; mi++) {
                    mma_tf32(acc[mi][ni], ah[mi], bh0, bh1);
                    mma_tf32(acc[mi][ni], ah[mi], bl0, bl1);
                    mma_tf32(acc[mi][ni], al[mi], bh0, bh1);
                }
            }
        }
        __syncthreads();
    }
    float* C = g_gram + (long)d * M_ * M_;
    #pragma unroll
    for (int mi = 0; mi < 2; mi++)
        #pragma unroll
        for (int h = 0; h < 2; h++) {
            int row = m0 + wm + mi * 16 + h * 8 + g;
            #pragma unroll
            for (int ni = 0; ni < 4; ni++) {
                int col = n0 + wn + ni * 8 + 2 * c;
                float2 o = make_float2(acc[mi][ni][h*2+0], acc[mi][ni][h*2+1]);
                *(float2*)(C + (long)row * M_ + col) = o;
            }
        }
}

// ---------------- prep: gram diag extraction + zero accumulators ------------
__global__ void prep_kernel() {
    int k = blockIdx.x * 256 + threadIdx.x;
    if (k < D_ * M_) {
        int d = k / M_, i = k % M_;
        g_sq[k] = g_gram[(long)d * M_ * M_ + (long)i * M_ + i];
    } else if (k < 2 * D_ * M_) {
        g_rowsum[k - D_ * M_] = 0.f;
    } else if (k < 3 * D_ * M_) {
        g_colsum[k - 2 * D_ * M_] = 0.f;
    } else if (k == 3 * D_ * M_) {
        g_lossacc = 0.f;
        g_loss_ct = 0;
    }
}

// ---------------- bf16 hi/lo split tensor-core GEMM -------------------------
// C = A(row-major m×k) @ B(row-major k×n).  TERMS: 3 = hh+hl+lh (generic),
// 2 = hh+hl (A exact in bf16, e.g. 0/1 incidence).
// GATHER: 1 => A rows gathered from t/a/v (X projection).
// EPI: 1 +bias, 2 /divrow, 3 +bias,relu,remap->out_cat
template<int EPI, int GATHER, int TERMS>
__global__ __launch_bounds__(128)
void gemm_bf(const float* __restrict__ Ag, const float* __restrict__ Bg,
             float* __restrict__ Cg,
             int M, int N, int K, int lda, int ldb,
             long sA, long sB, long sC,
             const float* __restrict__ bias,
             const float* __restrict__ divrow,
             float* __restrict__ outp,
             const float* __restrict__ t, const float* __restrict__ a,
             const float* __restrict__ v) {
    __shared__ __nv_bfloat16 Ah[64*40], Al[64*40];
    __shared__ __nv_bfloat16 Bh[32*72], Bl[32*72];
    const int b = blockIdx.z;
    const int m0 = blockIdx.y * 64, n0 = blockIdx.x * 64;
    const float* A;
    if (GATHER == 1) {
        const float* srcs[3] = {t, a, v};
        int d = m0 / M_, jm0 = m0 % M_;
        A = srcs[jm0 >> 6] + (long)d * L_ * DIM_;
    } else {
        A = Ag + (long)b * sA + (long)m0 * lda;
    }
    const float* B = Bg + (long)b * sB;
    const int tid = threadIdx.x, lane = tid & 31, wid = tid >> 5;
    const int wm = (wid >> 1) * 32, wn = (wid & 1) * 32;
    const int g = lane >> 2, c = lane & 3;

    unsigned ah_b = (unsigned)__cvta_generic_to_shared(Ah);
    unsigned al_b = (unsigned)__cvta_generic_to_shared(Al);
    unsigned bh_b = (unsigned)__cvta_generic_to_shared(Bh);
    unsigned bl_b = (unsigned)__cvta_generic_to_shared(Bl);

    float acc[2][4][4];
    #pragma unroll
    for (int mi = 0; mi < 2; mi++)
        #pragma unroll
        for (int ni = 0; ni < 4; ni++)
            #pragma unroll
            for (int r = 0; r < 4; r++) acc[mi][ni][r] = 0.f;

    for (int k0 = 0; k0 < K; k0 += 32) {
        #pragma unroll
        for (int it = 0; it < 4; it++) {
            int idx = it * 128 + tid;
            // A tile: 64 rows x 32 k
            int m = idx >> 3, kc = (idx & 7) << 2;
            float4 t4 = *(const float4*)(A + (long)m * lda + k0 + kc);
            __nv_bfloat162 h01 = __float22bfloat162_rn(make_float2(t4.x, t4.y));
            __nv_bfloat162 h23 = __float22bfloat162_rn(make_float2(t4.z, t4.w));
            *(uint2*)&Ah[m*40 + kc] = make_uint2(b2u(h01), b2u(h23));
            if (TERMS == 3) {
                __nv_bfloat162 l01 = __float22bfloat162_rn(make_float2(
                    t4.x - __low2float(h01), t4.y - __high2float(h01)));
                __nv_bfloat162 l23 = __float22bfloat162_rn(make_float2(
                    t4.z - __low2float(h23), t4.w - __high2float(h23)));
                *(uint2*)&Al[m*40 + kc] = make_uint2(b2u(l01), b2u(l23));
            }
            // B tile: 32 k x 64 n
            int k = idx >> 4, nc = (idx & 15) << 2;
            float4 u4 = *(const float4*)(B + (long)(k0 + k) * ldb + n0 + nc);
            __nv_bfloat162 bh01 = __float22bfloat162_rn(make_float2(u4.x, u4.y));
            __nv_bfloat162 bh23 = __float22bfloat162_rn(make_float2(u4.z, u4.w));
            *(uint2*)&Bh[k*72 + nc] = make_uint2(b2u(bh01), b2u(bh23));
            __nv_bfloat162 bl01 = __float22bfloat162_rn(make_float2(
                u4.x - __low2float(bh01), u4.y - __high2float(bh01)));
            __nv_bfloat162 bl23 = __float22bfloat162_rn(make_float2(
                u4.z - __low2float(bh23), u4.w - __high2float(bh23)));
            *(uint2*)&Bl[k*72 + nc] = make_uint2(b2u(bl01), b2u(bl23));
        }
        __syncthreads();
        #pragma unroll
        for (int kk = 0; kk < 32; kk += 16) {
            unsigned ah[2][4], al[2][4];
            #pragma unroll
            for (int mi = 0; mi < 2; mi++) {
                int aoff = (wm + mi*16 + (lane & 15)) * 40 + kk + (lane >> 4) * 8;
                ldsm4(ah[mi], ah_b + 2u * aoff);
                if (TERMS == 3) ldsm4(al[mi], al_b + 2u * aoff);
            }
            #pragma unroll
            for (int ntp = 0; ntp < 2; ntp++) {
                int boff = (kk + ((lane >> 3) & 1) * 8 + (lane & 7)) * 72
                         + wn + ntp * 16 + (lane >> 4) * 8;
                unsigned bh[4], bl[4];
                ldsm4t(bh, bh_b + 2u * boff);
                ldsm4t(bl, bl_b + 2u * boff);
                #pragma unroll
                for (int mi = 0; mi < 2; mi++) {
                    mma16816(acc[mi][2*ntp+0], ah[mi], bh[0], bh[1]);
                    mma16816(acc[mi][2*ntp+1], ah[mi], bh[2], bh[3]);
                    mma16816(acc[mi][2*ntp+0], ah[mi], bl[0], bl[1]);
                    mma16816(acc[mi][2*ntp+1], ah[mi], bl[2], bl[3]);
                    if (TERMS == 3) {
                        mma16816(acc[mi][2*ntp+0], al[mi], bh[0], bh[1]);
                        mma16816(acc[mi][2*ntp+1], al[mi], bh[2], bh[3]);
                    }
                }
            }
        }
        __syncthreads();
    }

    #pragma unroll
    for (int mi = 0; mi < 2; mi++)
        #pragma unroll
        for (int h = 0; h < 2; h++) {
            int row = m0 + wm + mi * 16 + h * 8 + g;
            float dr = 1.f;
            if (EPI == 2) dr = divrow[(long)b * M + row];
            #pragma unroll
            for (int ni = 0; ni < 4; ni++) {
                int col = n0 + wn + ni * 8 + 2 * c;
                float x0 = acc[mi][ni][h*2+0];
                float x1 = acc[mi][ni][h*2+1];
                if (EPI == 1 || EPI == 3) {
                    float2 bb = *(const float2*)(bias + col);
                    x0 += bb.x; x1 += bb.y;
                }
                if (EPI == 2) { x0 /= dr; x1 /= dr; }
                if (EPI == 3) { x0 = fmaxf(x0, 0.f); x1 = fmaxf(x1, 0.f); }
                float2 o = make_float2(x0, x1);
                if (EPI == 3) {
                    int d = row / M_, jm = row % M_;
                    long base = ((long)(d * L_ + (jm & 63)) * (3 * G_)) + (jm >> 6) * G_ + col;
                    *(float2*)(outp + base) = o;
                } else {
                    float* Cb = Cg + (long)b * sC;
                    *(float2*)(Cb + (long)row * N + col) = o;
                }
            }
        }
}

// ---------------- top-k + H + Ht + deg_e ------------------------------------
__global__ void topk_kernel() {
    int gw = (blockIdx.x * blockDim.x + threadIdx.x) >> 5;
    int lane = threadIdx.x & 31;
    if (gw >= D_ * M_) return;
    int d = gw / M_, i = gw % M_;
    const float* gr = g_gram + (long)d * M_ * M_ + (long)i * M_;
    const float* sq = g_sq + d * M_;
    float gii = sq[i];
    float vals[6];
    #pragma unroll
    for (int q = 0; q < 6; q++) {
        int j = q * 32 + lane;
        float dd = gii + sq[j] - 2.f * gr[j];
        vals[q] = fmaxf(dd, 0.f);
    }
    unsigned selmask = 0;
    for (int it = 0; it < KTOP; it++) {
        float bv = vals[0]; int bq = 0;
        #pragma unroll
        for (int q = 1; q < 6; q++)
            if (vals[q] < bv) { bv = vals[q]; bq = q; }   // lower j wins ties
        int bj = bq * 32 + lane;
        #pragma unroll
        for (int off = 16; off > 0; off >>= 1) {
            float ov = __shfl_xor_sync(0xffffffffu, bv, off);
            int   oj = __shfl_xor_sync(0xffffffffu, bj, off);
            if (ov < bv || (ov == bv && oj < bj)) { bv = ov; bj = oj; }
        }
        if ((bj & 31) == lane) { vals[bj >> 5] = 3.402823466e38f; selmask |= 1u << (bj >> 5); }
    }
    int u = i / 3;
    float cnt = 0.f;
    float* Hrow = g_H + ((long)d * M_ + i) * M_;
    float* Htb  = g_Ht + (long)d * M_ * M_;
    #pragma unroll
    for (int q = 0; q < 6; q++) {
        int j = q * 32 + lane;
        bool sel = (selmask >> q) & 1u;
        bool cen = (j == u) || (j == u + L_) || (j == u + 2 * L_);
        float h = (sel || cen) ? 1.f : 0.f;
        Hrow[j] = h;
        Htb[(long)j * M_ + i] = h;
        cnt += h;
    }
    #pragma unroll
    for (int off = 16; off > 0; off >>= 1) cnt += __shfl_xor_sync(0xffffffffu, cnt, off);
    if (lane == 0) g_dege[d * M_ + i] = cnt;
}

// deg_v[n] = sum_e H[e][n] = row sums of Ht (coalesced)
__global__ void degv_kernel() {
    int gw = (blockIdx.x * blockDim.x + threadIdx.x) >> 5;
    int lane = threadIdx.x & 31;
    if (gw >= D_ * M_) return;
    const float* r = g_Ht + (long)gw * M_;
    float s = 0.f;
    #pragma unroll
    for (int q = 0; q < 6; q++) s += r[q * 32 + lane];
    #pragma unroll
    for (int off = 16; off > 0; off >>= 1) s += __shfl_xor_sync(0xffffffffu, s, off);
    if (lane == 0) g_degv[gw] = s;
}

// ---------------- row normalization (fp32 + bf16 outputs) -------------------
__global__ void norm_kernel(const float* __restrict__ outc) {
    int gw = (blockIdx.x * blockDim.x + threadIdx.x) >> 5;
    int lane = threadIdx.x & 31;
    if (gw >= 3 * N_) return;
    int q = gw / N_, r = gw % N_;
    const float* src = outc + (long)r * (3 * G_) + q * G_;
    float vv[8]; float s = 0.f;
    #pragma unroll
    for (int c = 0; c < 8; c++) { vv[c] = src[lane + 32 * c]; s += vv[c] * vv[c]; }
    #pragma unroll
    for (int off = 16; off > 0; off >>= 1) s += __shfl_xor_sync(0xffffffffu, s, off);
    float inv = 1.f / (sqrtf(s) + 1e-8f);
    float* dst = g_xn + ((long)q * N_ + r) * G_;
    __nv_bfloat16* dsth = g_xnh + ((long)q * N_ + r) * G_;
    #pragma unroll
    for (int c = 0; c < 8; c++) {
        float x = vv[c] * inv;
        dst[lane + 32 * c] = x;
        dsth[lane + 32 * c] = __float2bfloat16(x);
    }
}

#define STR 40   // shared row stride in halves (32 data + 8 pad)

__global__ __launch_bounds__(256)
void sim_mma_kernel() {
    const int pxA[3] = {0, 0, 1};
    const int pyA[3] = {1, 2, 2};
    const int pair = blockIdx.z;
    const __nv_bfloat16* Xm = g_xnh + (long)pxA[pair] * N_ * G_;
    const __nv_bfloat16* Ym = g_xnh + (long)pyA[pair] * N_ * G_;
    const int i0 = blockIdx.y * 128;
    const int j0 = blockIdx.x * 128;

    __shared__ __nv_bfloat16 As[128 * STR];
    __shared__ __nv_bfloat16 Bs[128 * STR];
    __shared__ float sRow[128];
    __shared__ float sCol[128];

    const int tid = threadIdx.x;
    const int lane = tid & 31;
    const int wid = tid >> 5;
    const int wm = wid >> 1;        // 0..3 -> 32-row strip
    const int wn = wid & 1;         // 0..1 -> 64-col strip
    const int g = lane >> 2;
    const int q = lane >> 3, rr = lane & 7;

    if (tid < 128) { sRow[tid] = 0.f; sCol[tid] = 0.f; }

    unsigned as_b = (unsigned)__cvta_generic_to_shared(As);
    unsigned bs_b = (unsigned)__cvta_generic_to_shared(Bs);
    int aoff[2], boff[4];
    #pragma unroll
    for (int mi = 0; mi < 2; mi++)
        aoff[mi] = (wm * 32 + mi * 16 + (q & 1) * 8 + rr) * STR + (q >> 1) * 8;
    #pragma unroll
    for (int np = 0; np < 4; np++)
        boff[np] = (wn * 64 + np * 16 + (q >> 1) * 8 + rr) * STR + (q & 1) * 8;

    float acc[2][8][4];
    #pragma unroll
    for (int mi = 0; mi < 2; mi++)
        #pragma unroll
        for (int ni = 0; ni < 8; ni++)
            #pragma unroll
            for (int r = 0; r < 4; r++) acc[mi][ni][r] = 0.f;

    for (int k0 = 0; k0 < G_; k0 += 32) {
        #pragma unroll
        for (int qq0 = 0; qq0 < 2; qq0++) {
            int qq = tid * 2 + qq0;         // 0..511
            int row = qq >> 2, kc = qq & 3; // 128 rows x 4 chunks of 8 halves
            *(uint4*)&As[row * STR + kc * 8] =
                *(const uint4*)(Xm + (long)(i0 + row) * G_ + k0 + kc * 8);
            *(uint4*)&Bs[row * STR + kc * 8] =
                *(const uint4*)(Ym + (long)(j0 + row) * G_ + k0 + kc * 8);
        }
        __syncthreads();
        #pragma unroll
        for (int kk = 0; kk < 32; kk += 16) {
            unsigned a[2][4];
            #pragma unroll
            for (int mi = 0; mi < 2; mi++)
                ldsm4(a[mi], as_b + 2u * (aoff[mi] + kk));
            #pragma unroll
            for (int np = 0; np < 4; np++) {
                unsigned bb[4];
                ldsm4(bb, bs_b + 2u * (boff[np] + kk));
                mma16816(acc[0][2*np+0], a[0], bb[0], bb[1]);
                mma16816(acc[1][2*np+0], a[1], bb[0], bb[1]);
                mma16816(acc[0][2*np+1], a[0], bb[2], bb[3]);
                mma16816(acc[1][2*np+1], a[1], bb[2], bb[3]);
            }
        }
        __syncthreads();
    }

    // exp(sim/tau)
    float e[2][8][4];
    #pragma unroll
    for (int mi = 0; mi < 2; mi++)
        #pragma unroll
        for (int ni = 0; ni < 8; ni++)
            #pragma unroll
            for (int r = 0; r < 4; r++)
                e[mi][ni][r] = __expf(acc[mi][ni][r] * INV_TAU);

    // row partial sums
    #pragma unroll
    for (int mi = 0; mi < 2; mi++)
        #pragma unroll
        for (int h = 0; h < 2; h++) {
            float s = 0.f;
            #pragma unroll
            for (int ni = 0; ni < 8; ni++)
                s += h ? (e[mi][ni][2] + e[mi][ni][3])
                       : (e[mi][ni][0] + e[mi][ni][1]);
            s += __shfl_xor_sync(0xffffffffu, s, 1);
            s += __shfl_xor_sync(0xffffffffu, s, 2);
            if ((lane & 3) == 0)
                atomicAdd(&sRow[wm * 32 + mi * 16 + h * 8 + g], s);
        }

    // col partial sums
    #pragma unroll
    for (int ni = 0; ni < 8; ni++)
        #pragma unroll
        for (int p = 0; p < 2; p++) {
            float s = e[0][ni][p] + e[0][ni][p + 2] + e[1][ni][p] + e[1][ni][p + 2];
            s += __shfl_xor_sync(0xffffffffu, s, 4);
            s += __shfl_xor_sync(0xffffffffu, s, 8);
            s += __shfl_xor_sync(0xffffffffu, s, 16);
            if (lane < 4)
                atomicAdd(&sCol[wn * 64 + ni * 8 + lane * 2 + p], s);
        }

    __syncthreads();
    if (tid < 128) {
        atomicAdd(&g_rowsum[pair * N_ + i0 + tid], sRow[tid]);
        atomicAdd(&g_colsum[pair * N_ + j0 + tid], sCol[tid]);
    }
}

// ---------------- diagonal + loss accumulation + final write ----------------
__global__ void loss_kernel(float* __restrict__ out, int idx) {
    int gw = (blockIdx.x * blockDim.x + threadIdx.x) >> 5;
    int lane = threadIdx.x & 31;
    int p = gw / N_, i = gw % N_;
    const int pxA[3] = {0, 0, 1};
    const int pyA[3] = {1, 2, 2};
    const float* x = g_xn + ((long)pxA[p] * N_ + i) * G_;
    const float* y = g_xn + ((long)pyA[p] * N_ + i) * G_;
    float dot = 0.f;
    #pragma unroll
    for (int c = 0; c < 8; c++) dot += x[lane + 32 * c] * y[lane + 32 * c];
    #pragma unroll
    for (int off = 16; off > 0; off >>= 1) dot += __shfl_xor_sync(0xffffffffu, dot, off);
    if (lane == 0) {
        float ci = 2.f * dot * INV_TAU - logf(g_rowsum[p * N_ + i]) - logf(g_colsum[p * N_ + i]);
        atomicAdd(&g_lossacc, ci);
    }
    __syncthreads();
    if (threadIdx.x == 0) {
        __threadfence();
        int c = atomicAdd(&g_loss_ct, 1);
        if (c == (int)gridDim.x - 1)
            out[idx] = -(*(volatile float*)&g_lossacc) / (float)(2 * N_ * 3);
    }
}

// ---------------- launch ----------------------------------------------------
extern "C" void kernel_launch(void* const* d_in, const int* in_sizes, int n_in,
                              void* d_out, int out_size) {
    const float* t   = (const float*)d_in[0];
    const float* a   = (const float*)d_in[1];
    const float* v   = (const float*)d_in[2];
    const float* Wfc = (const float*)d_in[3];
    const float* bfc = (const float*)d_in[4];
    const float* Wh  = (const float*)d_in[5];
    const float* bh  = (const float*)d_in[6];
    float* out = (float*)d_out;

    void *ph, *pht, *pde, *pdv, *px, *pe, *py;
    cudaGetSymbolAddress(&ph,  g_H);
    cudaGetSymbolAddress(&pht, g_Ht);
    cudaGetSymbolAddress(&pde, g_dege);
    cudaGetSymbolAddress(&pdv, g_degv);
    cudaGetSymbolAddress(&px,  g_X);
    cudaGetSymbolAddress(&pe,  g_E);
    cudaGetSymbolAddress(&py,  g_Y);
    float* H = (float*)ph;    float* Ht = (float*)pht;
    float* dege = (float*)pde; float* degv = (float*)pdv;
    float* X = (float*)px;    float* E = (float*)pe;  float* Y = (float*)py;

    // gram[d] = feat_d @ feat_d^T, 3x-tf32 (fp32-equivalent for top-k)
    gram_tc<<<dim3(3, 3, D_), 128>>>(t, a, v);

    // diag extraction + accumulator zeroing
    prep_kernel<<<145, 256>>>();

    topk_kernel<<<1536, 256>>>();
    degv_kernel<<<1536, 256>>>();

    // X = feat @ W_fc + b_fc   (12288x256x512), bf16 3-term split, A gathered
    gemm_bf<1,1,3><<<dim3(4, 192, 1), 128>>>(nullptr, Wfc, X,
        D_*M_, G_, DIM_, DIM_, G_, 0, 0, 0, bfc, nullptr, nullptr, t, a, v);

    // E = (H @ X) / deg_e   (A exact 0/1 -> 2 terms)
    gemm_bf<2,0,2><<<dim3(4, 3, D_), 128>>>(H, X, E,
        M_, G_, M_, M_, G_,
        (long)M_*M_, (long)M_*G_, (long)M_*G_, nullptr, dege, nullptr, t, a, v);

    // Y = (Ht @ E) / deg_v
    gemm_bf<2,0,2><<<dim3(4, 3, D_), 128>>>(Ht, E, Y,
        M_, G_, M_, M_, G_,
        (long)M_*M_, (long)M_*G_, (long)M_*G_, nullptr, degv, nullptr, t, a, v);

    // out = relu(Y @ W_h + b_h), remapped into out_cat layout in d_out
    gemm_bf<3,0,3><<<dim3(4, 192, 1), 128>>>(Y, Wh, nullptr,
        D_*M_, G_, G_, G_, G_, 0, 0, 0, bh, nullptr, out, t, a, v);

    norm_kernel<<<1536, 256>>>(out);

    // all three contrastive sims on tensor cores, fused exp/row/col sums
    sim_mma_kernel<<<dim3(32, 32, 3), 256>>>();

    // loss + final write (fused finish via atomic block counter)
    loss_kernel<<<1536, 256>>>(out, out_size - 1);
}

// round 16
// speedup vs baseline: 1.0486x; 1.0486x over previous
#include <cuda_runtime.h>
#include <cuda_bf16.h>
#include <math.h>

// Problem constants
#define D_    64
#define L_    64
#define M_    192          // 3*L nodes per dialogue
#define DIM_  512
#define G_    256
#define N_    4096         // D*L
#define KTOP  12           // int(64*0.2)
#define INV_TAU (1.0f/0.07f)

// ---------------- scratch (static __device__ arrays: allocation-free) ------
__device__ float g_gram[D_*M_*M_];       // per-dialogue gram (fp32)
__device__ float g_sq[D_*M_];            // gram diagonal
__device__ __nv_bfloat16 g_Hb [D_*M_*M_];   // incidence 0/1 bf16 [d][e][n]
__device__ __nv_bfloat16 g_Htb[D_*M_*M_];   // transpose [d][n][e]
__device__ float g_dege[D_*M_];
__device__ float g_degv[D_*M_];
// preconverted bf16 hi/lo operands
__device__ __nv_bfloat16 g_fh[D_*M_*DIM_], g_fl[D_*M_*DIM_];   // feat
__device__ __nv_bfloat16 g_Wfch[DIM_*G_],  g_Wfcl[DIM_*G_];
__device__ __nv_bfloat16 g_Whh[G_*G_],     g_Whl[G_*G_];
__device__ __nv_bfloat16 g_Xh[D_*M_*G_],   g_Xl[D_*M_*G_];
__device__ __nv_bfloat16 g_Eh[D_*M_*G_],   g_El[D_*M_*G_];
__device__ __nv_bfloat16 g_Yh[D_*M_*G_],   g_Yl[D_*M_*G_];
// loss path
__device__ float g_xn[3*N_*G_];
__device__ __nv_bfloat16 g_xnh[3*N_*G_];
__device__ float g_rowsum[3*N_];
__device__ float g_colsum[3*N_];
__device__ float g_lossacc;
__device__ int   g_loss_ct;

// ---------------- helpers ---------------------------------------------------
__device__ __forceinline__ unsigned f2tf(float x) {
    unsigned u;
    asm("cvt.rna.tf32.f32 %0, %1;" : "=r"(u) : "f"(x));
    return u;
}
__device__ __forceinline__ void mma_tf32(float* c, const unsigned* a,
                                         unsigned b0, unsigned b1) {
    asm volatile(
        "mma.sync.aligned.m16n8k8.row.col.f32.tf32.tf32.f32 "
        "{%0,%1,%2,%3},{%4,%5,%6,%7},{%8,%9},{%0,%1,%2,%3};"
        : "+f"(c[0]), "+f"(c[1]), "+f"(c[2]), "+f"(c[3])
        : "r"(a[0]), "r"(a[1]), "r"(a[2]), "r"(a[3]), "r"(b0), "r"(b1));
}
__device__ __forceinline__ void mma16816(float* c, const unsigned* a,
                                         unsigned b0, unsigned b1) {
    asm volatile(
        "mma.sync.aligned.m16n8k16.row.col.f32.bf16.bf16.f32 "
        "{%0,%1,%2,%3},{%4,%5,%6,%7},{%8,%9},{%0,%1,%2,%3};"
        : "+f"(c[0]), "+f"(c[1]), "+f"(c[2]), "+f"(c[3])
        : "r"(a[0]), "r"(a[1]), "r"(a[2]), "r"(a[3]), "r"(b0), "r"(b1));
}
__device__ __forceinline__ void ldsm4(unsigned* r, unsigned addr) {
    asm volatile("ldmatrix.sync.aligned.m8n8.x4.shared.b16 {%0,%1,%2,%3},[%4];"
                 : "=r"(r[0]), "=r"(r[1]), "=r"(r[2]), "=r"(r[3]) : "r"(addr));
}
__device__ __forceinline__ void ldsm4t(unsigned* r, unsigned addr) {
    asm volatile("ldmatrix.sync.aligned.m8n8.x4.trans.shared.b16 {%0,%1,%2,%3},[%4];"
                 : "=r"(r[0]), "=r"(r[1]), "=r"(r[2]), "=r"(r[3]) : "r"(addr));
}
__device__ __forceinline__ unsigned b2u(__nv_bfloat162 h) {
    return *reinterpret_cast<unsigned*>(&h);
}

// convert 8 contiguous floats to bf16 hi/lo (uint4 each)
__device__ __forceinline__ void cvt8hl(const float* s,
                                       __nv_bfloat16* hd, __nv_bfloat16* ld) {
    float4 x0 = *(const float4*)s;
    float4 x1 = *(const float4*)(s + 4);
    float xs[8] = {x0.x, x0.y, x0.z, x0.w, x1.x, x1.y, x1.z, x1.w};
    __nv_bfloat162 h[4], l[4];
    #pragma unroll
    for (int p = 0; p < 4; p++) {
        float a = xs[2*p], b = xs[2*p+1];
        h[p] = __float22bfloat162_rn(make_float2(a, b));
        l[p] = __float22bfloat162_rn(make_float2(a - __low2float(h[p]),
                                                 b - __high2float(h[p])));
    }
    *(uint4*)hd = make_uint4(b2u(h[0]), b2u(h[1]), b2u(h[2]), b2u(h[3]));
    *(uint4*)ld = make_uint4(b2u(l[0]), b2u(l[1]), b2u(l[2]), b2u(l[3]));
}

// ---------------- precvt: feat/W -> bf16 hi/lo, zero accumulators -----------
#define NF8  (D_*M_*DIM_/8)     // 786432
#define NW1  (DIM_*G_/8)        // 16384
#define NW2  (G_*G_/8)          // 8192
#define NZ   (3*N_/4)           // 3072 float4 per accumulator array
__global__ void precvt_kernel(const float* __restrict__ t,
                              const float* __restrict__ a,
                              const float* __restrict__ v,
                              const float* __restrict__ Wfc,
                              const float* __restrict__ Wh) {
    long gid = (long)blockIdx.x * 256 + threadIdx.x;
    // DETERMINISM FIX: reset loss accumulators from a thread that is
    // guaranteed in-range (gid 0). The old `gid == NF8+NW1+NW2+2*NZ` clause
    // was one past the grid end, so the reset never executed and graph
    // replays accumulated/never re-fired the final loss write.
    if (gid == 0) { g_lossacc = 0.f; g_loss_ct = 0; }
    if (gid < NF8) {
        long base = gid * 8;
        int row = (int)(gid >> 6);           // base/512
        int k   = ((int)gid & 63) << 3;
        int d = row / M_, jm = row % M_;
        const float* srcs[3] = {t, a, v};
        const float* src = srcs[jm >> 6] + ((long)(d * L_ + (jm & 63))) * DIM_ + k;
        cvt8hl(src, g_fh + base, g_fl + base);
    } else if (gid < NF8 + NW1) {
        long base = (gid - NF8) * 8;
        cvt8hl(Wfc + base, g_Wfch + base, g_Wfcl + base);
    } else if (gid < NF8 + NW1 + NW2) {
        long base = (gid - NF8 - NW1) * 8;
        cvt8hl(Wh + base, g_Whh + base, g_Whl + base);
    } else if (gid < NF8 + NW1 + NW2 + NZ) {
        ((float4*)g_rowsum)[gid - NF8 - NW1 - NW2] = make_float4(0,0,0,0);
    } else if (gid < NF8 + NW1 + NW2 + 2*NZ) {
        ((float4*)g_colsum)[gid - NF8 - NW1 - NW2 - NZ] = make_float4(0,0,0,0);
    }
}

// ---------------- 3x-tf32 batched gram: gram[d] = feat_d @ feat_d^T ---------
// PROVEN version (R5/R9/R10 passing). Residual ~5e-6 abs -> top-k safe.
// Gathers rows directly from t/a/v; writes diagonal to g_sq in epilogue.
__global__ __launch_bounds__(128)
void gram_tc(const float* __restrict__ t, const float* __restrict__ a,
             const float* __restrict__ v) {
    __shared__ unsigned Ah[64*36], Al[64*36], Bh[64*36], Bl[64*36];
    const int d = blockIdx.z;
    const int m0 = blockIdx.y * 64, n0 = blockIdx.x * 64;
    const float* srcs[3] = {t, a, v};
    const float* FA = srcs[m0 >> 6] + (long)d * L_ * DIM_;
    const float* FB = srcs[n0 >> 6] + (long)d * L_ * DIM_;
    const int tid = threadIdx.x, lane = tid & 31, wid = tid >> 5;
    const int wm = (wid >> 1) * 32, wn = (wid & 1) * 32;
    const int g = lane >> 2, c = lane & 3;
    float acc[2][4][4];
    #pragma unroll
    for (int mi = 0; mi < 2; mi++)
        #pragma unroll
        for (int ni = 0; ni < 4; ni++)
            #pragma unroll
            for (int r = 0; r < 4; r++) acc[mi][ni][r] = 0.f;

    for (int k0 = 0; k0 < DIM_; k0 += 32) {
        #pragma unroll
        for (int it = 0; it < 4; it++) {
            int idx = it * 128 + tid;
            int m = idx >> 3, kc = (idx & 7) << 2;
            float4 t4 = *(const float4*)(FA + (long)m * DIM_ + k0 + kc);
            float xs[4] = {t4.x, t4.y, t4.z, t4.w};
            #pragma unroll
            for (int j = 0; j < 4; j++) {
                unsigned h = f2tf(xs[j]);
                Ah[m*36 + kc + j] = h;
                Al[m*36 + kc + j] = f2tf(xs[j] - __uint_as_float(h));
            }
            float4 u4 = *(const float4*)(FB + (long)m * DIM_ + k0 + kc);
            float ys[4] = {u4.x, u4.y, u4.z, u4.w};
            #pragma unroll
            for (int j = 0; j < 4; j++) {
                unsigned h = f2tf(ys[j]);
                Bh[m*36 + kc + j] = h;
                Bl[m*36 + kc + j] = f2tf(ys[j] - __uint_as_float(h));
            }
        }
        __syncthreads();
        #pragma unroll
        for (int kk = 0; kk < 32; kk += 8) {
            unsigned ah[2][4], al[2][4];
            #pragma unroll
            for (int mi = 0; mi < 2; mi++) {
                int rb = wm + mi * 16;
                ah[mi][0] = Ah[(rb+g)*36 + kk+c];   al[mi][0] = Al[(rb+g)*36 + kk+c];
                ah[mi][1] = Ah[(rb+8+g)*36 + kk+c]; al[mi][1] = Al[(rb+8+g)*36 + kk+c];
                ah[mi][2] = Ah[(rb+g)*36 + kk+c+4]; al[mi][2] = Al[(rb+g)*36 + kk+c+4];
                ah[mi][3] = Ah[(rb+8+g)*36 + kk+c+4]; al[mi][3] = Al[(rb+8+g)*36 + kk+c+4];
            }
            #pragma unroll
            for (int ni = 0; ni < 4; ni++) {
                int cb = wn + ni * 8 + g;
                unsigned bh0 = Bh[cb*36 + kk+c], bh1 = Bh[cb*36 + kk+c+4];
                unsigned bl0 = Bl[cb*36 + kk+c], bl1 = Bl[cb*36 + kk+c+4];
                #pragma unroll
                for (int mi = 0; mi < 2; mi++) {
                    mma_tf32(acc[mi][ni], ah[mi], bh0, bh1);
                    mma_tf32(acc[mi][ni], ah[mi], bl0, bl1);
                    mma_tf32(acc[mi][ni], al[mi], bh0, bh1);
                }
            }
        }
        __syncthreads();
    }
    float* C = g_gram + (long)d * M_ * M_;
    #pragma unroll
    for (int mi = 0; mi < 2; mi++)
        #pragma unroll
        for (int h = 0; h < 2; h++) {
            int row = m0 + wm + mi * 16 + h * 8 + g;
            #pragma unroll
            for (int ni = 0; ni < 4; ni++) {
                int col = n0 + wn + ni * 8 + 2 * c;
                float x0 = acc[mi][ni][h*2+0], x1 = acc[mi][ni][h*2+1];
                *(float2*)(C + (long)row * M_ + col) = make_float2(x0, x1);
                if (row == col)     g_sq[d * M_ + row] = x0;
                if (row == col + 1) g_sq[d * M_ + row] = x1;
            }
        }
}

// ---------------- top-k + H/Ht (bf16) + deg_e --------------------------------
__global__ void topk_kernel() {
    int gw = (blockIdx.x * blockDim.x + threadIdx.x) >> 5;
    int lane = threadIdx.x & 31;
    if (gw >= D_ * M_) return;
    int d = gw / M_, i = gw % M_;
    const float* gr = g_gram + (long)d * M_ * M_ + (long)i * M_;
    const float* sq = g_sq + d * M_;
    float gii = sq[i];
    float vals[6];
    #pragma unroll
    for (int q = 0; q < 6; q++) {
        int j = q * 32 + lane;
        float dd = gii + sq[j] - 2.f * gr[j];
        vals[q] = fmaxf(dd, 0.f);
    }
    unsigned selmask = 0;
    for (int it = 0; it < KTOP; it++) {
        float bv = vals[0]; int bq = 0;
        #pragma unroll
        for (int q = 1; q < 6; q++)
            if (vals[q] < bv) { bv = vals[q]; bq = q; }   // lower j wins ties
        int bj = bq * 32 + lane;
        #pragma unroll
        for (int off = 16; off > 0; off >>= 1) {
            float ov = __shfl_xor_sync(0xffffffffu, bv, off);
            int   oj = __shfl_xor_sync(0xffffffffu, bj, off);
            if (ov < bv || (ov == bv && oj < bj)) { bv = ov; bj = oj; }
        }
        if ((bj & 31) == lane) { vals[bj >> 5] = 3.402823466e38f; selmask |= 1u << (bj >> 5); }
    }
    int u = i / 3;
    float cnt = 0.f;
    __nv_bfloat16* Hrow = g_Hb + ((long)d * M_ + i) * M_;
    __nv_bfloat16* Htb  = g_Htb + (long)d * M_ * M_;
    const __nv_bfloat16 one = __float2bfloat16(1.f);
    const __nv_bfloat16 zero = __float2bfloat16(0.f);
    #pragma unroll
    for (int q = 0; q < 6; q++) {
        int j = q * 32 + lane;
        bool sel = (selmask >> q) & 1u;
        bool cen = (j == u) || (j == u + L_) || (j == u + 2 * L_);
        bool on = sel || cen;
        Hrow[j] = on ? one : zero;
        Htb[(long)j * M_ + i] = on ? one : zero;
        cnt += on ? 1.f : 0.f;
    }
    #pragma unroll
    for (int off = 16; off > 0; off >>= 1) cnt += __shfl_xor_sync(0xffffffffu, cnt, off);
    if (lane == 0) g_dege[d * M_ + i] = cnt;
}

// deg_v[n] = row sums of Ht (coalesced bf16)
__global__ void degv_kernel() {
    int gw = (blockIdx.x * blockDim.x + threadIdx.x) >> 5;
    int lane = threadIdx.x & 31;
    if (gw >= D_ * M_) return;
    const __nv_bfloat16* r = g_Htb + (long)gw * M_;
    float s = 0.f;
    #pragma unroll
    for (int q = 0; q < 6; q++) s += __bfloat162float(r[q * 32 + lane]);
    #pragma unroll
    for (int off = 16; off > 0; off >>= 1) s += __shfl_xor_sync(0xffffffffu, s, off);
    if (lane == 0) g_degv[gw] = s;
}

// ---------------- bf16 hi/lo GEMM, pure-bf16 operand loads -------------------
// C = A(row-major m×k) @ B(row-major k×n). A/B already bf16 hi(+lo).
// AL/BL: does A/B have a lo term. Terms: ah·bh [+ ah·bl if BL] [+ al·bh if AL].
// EPI: 1 +bias -> write Chi/Clo bf16; 2 /divrow -> write Chi/Clo;
//      3 +bias,relu,remap -> write fp32 out_cat
template<int EPI, int AL, int BL>
__global__ __launch_bounds__(128)
void gemm_bf(const __nv_bfloat16* __restrict__ Ahg, const __nv_bfloat16* __restrict__ Alg,
             const __nv_bfloat16* __restrict__ Bhg, const __nv_bfloat16* __restrict__ Blg,
             __nv_bfloat16* __restrict__ Chg, __nv_bfloat16* __restrict__ Clg,
             int Nc, int K, int lda, int ldb,
             long sA, long sB, long sC,
             const float* __restrict__ bias,
             const float* __restrict__ divrow,
             float* __restrict__ outp) {
    __shared__ __nv_bfloat16 Ah[64*40], Al[64*40];
    __shared__ __nv_bfloat16 Bh[32*72], Bl[32*72];
    const int b = blockIdx.z;
    const int m0 = blockIdx.y * 64, n0 = blockIdx.x * 64;
    const __nv_bfloat16* Ahp = Ahg + (long)b * sA + (long)m0 * lda;
    const __nv_bfloat16* Alp = AL ? (Alg + (long)b * sA + (long)m0 * lda) : nullptr;
    const __nv_bfloat16* Bhp = Bhg + (long)b * sB;
    const __nv_bfloat16* Blp = BL ? (Blg + (long)b * sB) : nullptr;
    const int tid = threadIdx.x, lane = tid & 31, wid = tid >> 5;
    const int wm = (wid >> 1) * 32, wn = (wid & 1) * 32;
    const int g = lane >> 2, c = lane & 3;

    unsigned ah_b = (unsigned)__cvta_generic_to_shared(Ah);
    unsigned al_b = (unsigned)__cvta_generic_to_shared(Al);
    unsigned bh_b = (unsigned)__cvta_generic_to_shared(Bh);
    unsigned bl_b = (unsigned)__cvta_generic_to_shared(Bl);

    float acc[2][4][4];
    #pragma unroll
    for (int mi = 0; mi < 2; mi++)
        #pragma unroll
        for (int ni = 0; ni < 4; ni++)
            #pragma unroll
            for (int r = 0; r < 4; r++) acc[mi][ni][r] = 0.f;

    for (int k0 = 0; k0 < K; k0 += 32) {
        #pragma unroll
        for (int it = 0; it < 2; it++) {
            int idx = it * 128 + tid;              // 0..255
            int row = idx >> 2, kc = (idx & 3) << 3;   // A: 64 rows x 4 chunks
            *(uint4*)&Ah[row * 40 + kc] = *(const uint4*)(Ahp + (long)row * lda + k0 + kc);
            if (AL)
                *(uint4*)&Al[row * 40 + kc] = *(const uint4*)(Alp + (long)row * lda + k0 + kc);
            int kr = idx >> 3, nc = (idx & 7) << 3;    // B: 32 k x 8 chunks
            *(uint4*)&Bh[kr * 72 + nc] = *(const uint4*)(Bhp + (long)(k0 + kr) * ldb + n0 + nc);
            if (BL)
                *(uint4*)&Bl[kr * 72 + nc] = *(const uint4*)(Blp + (long)(k0 + kr) * ldb + n0 + nc);
        }
        __syncthreads();
        #pragma unroll
        for (int kk = 0; kk < 32; kk += 16) {
            unsigned ah[2][4], al[2][4];
            #pragma unroll
            for (int mi = 0; mi < 2; mi++) {
                int aoff = (wm + mi*16 + (lane & 15)) * 40 + kk + (lane >> 4) * 8;
                ldsm4(ah[mi], ah_b + 2u * aoff);
                if (AL) ldsm4(al[mi], al_b + 2u * aoff);
            }
            #pragma unroll
            for (int ntp = 0; ntp < 2; ntp++) {
                int boff = (kk + ((lane >> 3) & 1) * 8 + (lane & 7)) * 72
                         + wn + ntp * 16 + (lane >> 4) * 8;
                unsigned bh[4], bl[4];
                ldsm4t(bh, bh_b + 2u * boff);
                if (BL) ldsm4t(bl, bl_b + 2u * boff);
                #pragma unroll
                for (int mi = 0; mi < 2; mi++) {
                    mma16816(acc[mi][2*ntp+0], ah[mi], bh[0], bh[1]);
                    mma16816(acc[mi][2*ntp+1], ah[mi], bh[2], bh[3]);
                    if (BL) {
                        mma16816(acc[mi][2*ntp+0], ah[mi], bl[0], bl[1]);
                        mma16816(acc[mi][2*ntp+1], ah[mi], bl[2], bl[3]);
                    }
                    if (AL) {
                        mma16816(acc[mi][2*ntp+0], al[mi], bh[0], bh[1]);
                        mma16816(acc[mi][2*ntp+1], al[mi], bh[2], bh[3]);
                    }
                }
            }
        }
        __syncthreads();
    }

    #pragma unroll
    for (int mi = 0; mi < 2; mi++)
        #pragma unroll
        for (int h = 0; h < 2; h++) {
            int row = m0 + wm + mi * 16 + h * 8 + g;
            float dr = 1.f;
            if (EPI == 2) dr = divrow[(long)b * M_ + row];
            #pragma unroll
            for (int ni = 0; ni < 4; ni++) {
                int col = n0 + wn + ni * 8 + 2 * c;
                float x0 = acc[mi][ni][h*2+0];
                float x1 = acc[mi][ni][h*2+1];
                if (EPI == 1 || EPI == 3) {
                    float2 bb = *(const float2*)(bias + col);
                    x0 += bb.x; x1 += bb.y;
                }
                if (EPI == 2) { x0 /= dr; x1 /= dr; }
                if (EPI == 3) {
                    x0 = fmaxf(x0, 0.f); x1 = fmaxf(x1, 0.f);
                    int d = row / M_, jm = row % M_;
                    long base = ((long)(d * L_ + (jm & 63)) * (3 * G_)) + (jm >> 6) * G_ + col;
                    *(float2*)(outp + base) = make_float2(x0, x1);
                } else {
                    long cidx = (long)b * sC + (long)row * Nc + col;
                    __nv_bfloat162 hh = __float22bfloat162_rn(make_float2(x0, x1));
                    __nv_bfloat162 ll = __float22bfloat162_rn(make_float2(
                        x0 - __low2float(hh), x1 - __high2float(hh)));
                    *(unsigned*)(Chg + cidx) = b2u(hh);
                    *(unsigned*)(Clg + cidx) = b2u(ll);
                }
            }
        }
}

// ---------------- row normalization (fp32 + bf16 outputs) -------------------
__global__ void norm_kernel(const float* __restrict__ outc) {
    int gw = (blockIdx.x * blockDim.x + threadIdx.x) >> 5;
    int lane = threadIdx.x & 31;
    if (gw >= 3 * N_) return;
    int q = gw / N_, r = gw % N_;
    const float* src = outc + (long)r * (3 * G_) + q * G_;
    float vv[8]; float s = 0.f;
    #pragma unroll
    for (int c = 0; c < 8; c++) { vv[c] = src[lane + 32 * c]; s += vv[c] * vv[c]; }
    #pragma unroll
    for (int off = 16; off > 0; off >>= 1) s += __shfl_xor_sync(0xffffffffu, s, off);
    float inv = 1.f / (sqrtf(s) + 1e-8f);
    float* dst = g_xn + ((long)q * N_ + r) * G_;
    __nv_bfloat16* dsth = g_xnh + ((long)q * N_ + r) * G_;
    #pragma unroll
    for (int c = 0; c < 8; c++) {
        float x = vv[c] * inv;
        dst[lane + 32 * c] = x;
        dsth[lane + 32 * c] = __float2bfloat16(x);
    }
}

#define STR 40   // shared row stride in halves (32 data + 8 pad)

__global__ __launch_bounds__(256)
void sim_mma_kernel() {
    const int pxA[3] = {0, 0, 1};
    const int pyA[3] = {1, 2, 2};
    const int pair = blockIdx.z;
    const __nv_bfloat16* Xm = g_xnh + (long)pxA[pair] * N_ * G_;
    const __nv_bfloat16* Ym = g_xnh + (long)pyA[pair] * N_ * G_;
    const int i0 = blockIdx.y * 128;
    const int j0 = blockIdx.x * 128;

    __shared__ __nv_bfloat16 As[128 * STR];
    __shared__ __nv_bfloat16 Bs[128 * STR];
    __shared__ float sRow[128];
    __shared__ float sCol[128];

    const int tid = threadIdx.x;
    const int lane = tid & 31;
    const int wid = tid >> 5;
    const int wm = wid >> 1;
    const int wn = wid & 1;
    const int g = lane >> 2;
    const int q = lane >> 3, rr = lane & 7;

    if (tid < 128) { sRow[tid] = 0.f; sCol[tid] = 0.f; }

    unsigned as_b = (unsigned)__cvta_generic_to_shared(As);
    unsigned bs_b = (unsigned)__cvta_generic_to_shared(Bs);
    int aoff[2], boff[4];
    #pragma unroll
    for (int mi = 0; mi < 2; mi++)
        aoff[mi] = (wm * 32 + mi * 16 + (q & 1) * 8 + rr) * STR + (q >> 1) * 8;
    #pragma unroll
    for (int np = 0; np < 4; np++)
        boff[np] = (wn * 64 + np * 16 + (q >> 1) * 8 + rr) * STR + (q & 1) * 8;

    float acc[2][8][4];
    #pragma unroll
    for (int mi = 0; mi < 2; mi++)
        #pragma unroll
        for (int ni = 0; ni < 8; ni++)
            #pragma unroll
            for (int r = 0; r < 4; r++) acc[mi][ni][r] = 0.f;

    for (int k0 = 0; k0 < G_; k0 += 32) {
        #pragma unroll
        for (int qq0 = 0; qq0 < 2; qq0++) {
            int qq = tid * 2 + qq0;
            int row = qq >> 2, kc = qq & 3;
            *(uint4*)&As[row * STR + kc * 8] =
                *(const uint4*)(Xm + (long)(i0 + row) * G_ + k0 + kc * 8);
            *(uint4*)&Bs[row * STR + kc * 8] =
                *(const uint4*)(Ym + (long)(j0 + row) * G_ + k0 + kc * 8);
        }
        __syncthreads();
        #pragma unroll
        for (int kk = 0; kk < 32; kk += 16) {
            unsigned a[2][4];
            #pragma unroll
            for (int mi = 0; mi < 2; mi++)
                ldsm4(a[mi], as_b + 2u * (aoff[mi] + kk));
            #pragma unroll
            for (int np = 0; np < 4; np++) {
                unsigned bb[4];
                ldsm4(bb, bs_b + 2u * (boff[np] + kk));
                mma16816(acc[0][2*np+0], a[0], bb[0], bb[1]);
                mma16816(acc[1][2*np+0], a[1], bb[0], bb[1]);
                mma16816(acc[0][2*np+1], a[0], bb[2], bb[3]);
                mma16816(acc[1][2*np+1], a[1], bb[2], bb[3]);
            }
        }
        __syncthreads();
    }

    float e[2][8][4];
    #pragma unroll
    for (int mi = 0; mi < 2; mi++)
        #pragma unroll
        for (int ni = 0; ni < 8; ni++)
            #pragma unroll
            for (int r = 0; r < 4; r++)
                e[mi][ni][r] = __expf(acc[mi][ni][r] * INV_TAU);

    #pragma unroll
    for (int mi = 0; mi < 2; mi++)
        #pragma unroll
        for (int h = 0; h < 2; h++) {
            float s = 0.f;
            #pragma unroll
            for (int ni = 0; ni < 8; ni++)
                s += h ? (e[mi][ni][2] + e[mi][ni][3])
                       : (e[mi][ni][0] + e[mi][ni][1]);
            s += __shfl_xor_sync(0xffffffffu, s, 1);
            s += __shfl_xor_sync(0xffffffffu, s, 2);
            if ((lane & 3) == 0)
                atomicAdd(&sRow[wm * 32 + mi * 16 + h * 8 + g], s);
        }

    #pragma unroll
    for (int ni = 0; ni < 8; ni++)
        #pragma unroll
        for (int p = 0; p < 2; p++) {
            float s = e[0][ni][p] + e[0][ni][p + 2] + e[1][ni][p] + e[1][ni][p + 2];
            s += __shfl_xor_sync(0xffffffffu, s, 4);
            s += __shfl_xor_sync(0xffffffffu, s, 8);
            s += __shfl_xor_sync(0xffffffffu, s, 16);
            if (lane < 4)
                atomicAdd(&sCol[wn * 64 + ni * 8 + lane * 2 + p], s);
        }

    __syncthreads();
    if (tid < 128) {
        atomicAdd(&g_rowsum[pair * N_ + i0 + tid], sRow[tid]);
        atomicAdd(&g_colsum[pair * N_ + j0 + tid], sCol[tid]);
    }
}

// ---------------- diagonal + loss accumulation + final write ----------------
__global__ void loss_kernel(float* __restrict__ out, int idx) {
    int gw = (blockIdx.x * blockDim.x + threadIdx.x) >> 5;
    int lane = threadIdx.x & 31;
    int p = gw / N_, i = gw % N_;
    const int pxA[3] = {0, 0, 1};
    const int pyA[3] = {1, 2, 2};
    const float* x = g_xn + ((long)pxA[p] * N_ + i) * G_;
    const float* y = g_xn + ((long)pyA[p] * N_ + i) * G_;
    float dot = 0.f;
    #pragma unroll
    for (int c = 0; c < 8; c++) dot += x[lane + 32 * c] * y[lane + 32 * c];
    #pragma unroll
    for (int off = 16; off > 0; off >>= 1) dot += __shfl_xor_sync(0xffffffffu, dot, off);
    if (lane == 0) {
        float ci = 2.f * dot * INV_TAU - logf(g_rowsum[p * N_ + i]) - logf(g_colsum[p * N_ + i]);
        atomicAdd(&g_lossacc, ci);
    }
    __syncthreads();
    if (threadIdx.x == 0) {
        __threadfence();
        int c = atomicAdd(&g_loss_ct, 1);
        if (c == (int)gridDim.x - 1)
            out[idx] = -(*(volatile float*)&g_lossacc) / (float)(2 * N_ * 3);
    }
}

// ---------------- launch ----------------------------------------------------
extern "C" void kernel_launch(void* const* d_in, const int* in_sizes, int n_in,
                              void* d_out, int out_size) {
    const float* t   = (const float*)d_in[0];
    const float* a   = (const float*)d_in[1];
    const float* v   = (const float*)d_in[2];
    const float* Wfc = (const float*)d_in[3];
    const float* bfc = (const float*)d_in[4];
    const float* Wh  = (const float*)d_in[5];
    const float* bh  = (const float*)d_in[6];
    float* out = (float*)d_out;

    void *phb, *phtb, *pde, *pdv, *pxh, *pxl, *peh, *pel, *pyh, *pyl,
         *pfh, *pfl, *pwfh, *pwfl, *pwhh, *pwhl;
    cudaGetSymbolAddress(&phb,  g_Hb);
    cudaGetSymbolAddress(&phtb, g_Htb);
    cudaGetSymbolAddress(&pde,  g_dege);
    cudaGetSymbolAddress(&pdv,  g_degv);
    cudaGetSymbolAddress(&pxh,  g_Xh);  cudaGetSymbolAddress(&pxl, g_Xl);
    cudaGetSymbolAddress(&peh,  g_Eh);  cudaGetSymbolAddress(&pel, g_El);
    cudaGetSymbolAddress(&pyh,  g_Yh);  cudaGetSymbolAddress(&pyl, g_Yl);
    cudaGetSymbolAddress(&pfh,  g_fh);  cudaGetSymbolAddress(&pfl, g_fl);
    cudaGetSymbolAddress(&pwfh, g_Wfch); cudaGetSymbolAddress(&pwfl, g_Wfcl);
    cudaGetSymbolAddress(&pwhh, g_Whh);  cudaGetSymbolAddress(&pwhl, g_Whl);
    __nv_bfloat16* Hb  = (__nv_bfloat16*)phb;
    __nv_bfloat16* Htb = (__nv_bfloat16*)phtb;
    float* dege = (float*)pde;  float* degv = (float*)pdv;
    __nv_bfloat16* Xh = (__nv_bfloat16*)pxh; __nv_bfloat16* Xl = (__nv_bfloat16*)pxl;
    __nv_bfloat16* Eh = (__nv_bfloat16*)peh; __nv_bfloat16* El = (__nv_bfloat16*)pel;
    __nv_bfloat16* Yh = (__nv_bfloat16*)pyh; __nv_bfloat16* Yl = (__nv_bfloat16*)pyl;
    __nv_bfloat16* fh = (__nv_bfloat16*)pfh; __nv_bfloat16* fl = (__nv_bfloat16*)pfl;
    __nv_bfloat16* Wfh = (__nv_bfloat16*)pwfh; __nv_bfloat16* Wfl = (__nv_bfloat16*)pwfl;
    __nv_bfloat16* Whh_ = (__nv_bfloat16*)pwhh; __nv_bfloat16* Whl_ = (__nv_bfloat16*)pwhl;

    // gram[d] = feat_d @ feat_d^T, 3x-tf32 (proven top-k-safe), diag -> g_sq
    gram_tc<<<dim3(3, 3, D_), 128>>>(t, a, v);

    // one-shot bf16 hi/lo conversions + accumulator zeroing
    precvt_kernel<<<3192, 256>>>(t, a, v, Wfc, Wh);

    topk_kernel<<<1536, 256>>>();
    degv_kernel<<<1536, 256>>>();

    // X = feat @ W_fc + b_fc  (AL=1, BL=1 -> 3 terms), writes Xh/Xl
    gemm_bf<1,1,1><<<dim3(4, 192, 1), 128>>>(fh, fl, Wfh, Wfl, Xh, Xl,
        G_, DIM_, DIM_, G_, 0, 0, 0, bfc, nullptr, nullptr);

    // E = (H @ X) / deg_e  (H exact -> AL=0, BL=1 -> 2 terms), writes Eh/El
    gemm_bf<2,0,1><<<dim3(4, 3, D_), 128>>>(Hb, nullptr, Xh, Xl, Eh, El,
        G_, M_, M_, G_, (long)M_*M_, (long)M_*G_, (long)M_*G_,
        nullptr, dege, nullptr);

    // Y = (Ht @ E) / deg_v, writes Yh/Yl
    gemm_bf<2,0,1><<<dim3(4, 3, D_), 128>>>(Htb, nullptr, Eh, El, Yh, Yl,
        G_, M_, M_, G_, (long)M_*M_, (long)M_*G_, (long)M_*G_,
        nullptr, degv, nullptr);

    // out = relu(Y @ W_h + b_h) remapped into out_cat (fp32)
    gemm_bf<3,1,1><<<dim3(4, 192, 1), 128>>>(Yh, Yl, Whh_, Whl_, nullptr, nullptr,
        G_, G_, G_, G_, 0, 0, 0, bh, nullptr, out);

    norm_kernel<<<1536, 256>>>(out);

    // all three contrastive sims on tensor cores, fused exp/row/col sums
    sim_mma_kernel<<<dim3(32, 32, 3), 256>>>();

    // loss + final write (fused finish via atomic block counter)
    loss_kernel<<<1536, 256>>>(out, out_size - 1);
}